// round 2
// baseline (speedup 1.0000x reference)
#include <cuda_runtime.h>

#define TT   8192
#define DIM  1024
#define NH   16
#define HD   64
#define B_   8
#define L_   1024

// scratch (allocation-free): Q,K,V in [B,H,L,D], attention out in [T, DIM]
__device__ float g_q[TT * DIM];
__device__ float g_k[TT * DIM];
__device__ float g_v[TT * DIM];
__device__ float g_att[TT * DIM];

// ---------------------------------------------------------------------------
// SGEMM: C[M,N] = A[M,K] @ B[K,N] + bias.  128x128x8 tile, 256 thr, 8x8/thread.
// SCATTER=1: instead of writing C, scatter into g_q/g_k/g_v ([B,H,L,D]).
// ---------------------------------------------------------------------------
template <int SCATTER>
__global__ __launch_bounds__(256) void sgemm_kernel(
    const float* __restrict__ A, const float* __restrict__ Bm,
    const float* __restrict__ bias, float* __restrict__ C,
    int M, int N, int K)
{
    __shared__ float As[8][128];
    __shared__ float Bs[8][128];

    const int tid = threadIdx.x;
    const int tm = tid >> 4;
    const int tn = tid & 15;
    const int rowBase = blockIdx.y * 128;
    const int colBase = blockIdx.x * 128;

    float acc[8][8];
#pragma unroll
    for (int i = 0; i < 8; i++)
#pragma unroll
        for (int j = 0; j < 8; j++) acc[i][j] = 0.f;

    const int aRow = tid >> 1;
    const int aCol = (tid & 1) << 2;
    const int bRow = tid >> 5;
    const int bCol = (tid & 31) << 2;

    const float* aPtr = A + (size_t)(rowBase + aRow) * K + aCol;
    const float* bPtr = Bm + (size_t)bRow * N + colBase + bCol;

    for (int k0 = 0; k0 < K; k0 += 8) {
        float4 a4 = *(const float4*)aPtr;
        float4 b4 = *(const float4*)bPtr;
        As[aCol + 0][aRow] = a4.x;
        As[aCol + 1][aRow] = a4.y;
        As[aCol + 2][aRow] = a4.z;
        As[aCol + 3][aRow] = a4.w;
        *(float4*)&Bs[bRow][bCol] = b4;
        __syncthreads();
#pragma unroll
        for (int kk = 0; kk < 8; kk++) {
            float ra[8], rb[8];
            *(float4*)&ra[0] = *(const float4*)&As[kk][tm * 8];
            *(float4*)&ra[4] = *(const float4*)&As[kk][tm * 8 + 4];
            *(float4*)&rb[0] = *(const float4*)&Bs[kk][tn * 8];
            *(float4*)&rb[4] = *(const float4*)&Bs[kk][tn * 8 + 4];
#pragma unroll
            for (int i = 0; i < 8; i++)
#pragma unroll
                for (int j = 0; j < 8; j++)
                    acc[i][j] = fmaf(ra[i], rb[j], acc[i][j]);
        }
        __syncthreads();
        aPtr += 8;
        bPtr += (size_t)8 * N;
    }

#pragma unroll
    for (int i = 0; i < 8; i++) {
        const int r = rowBase + tm * 8 + i;
#pragma unroll
        for (int j = 0; j < 8; j++) {
            const int c = colBase + tn * 8 + j;
            const float val = acc[i][j] + bias[c];
            if (SCATTER) {
                const int sec = c >> 10;            // 0=q 1=k 2=v
                const int h = (c >> 6) & (NH - 1);
                const int d = c & (HD - 1);
                const int b = r >> 10;
                const int l = r & (L_ - 1);
                const size_t idx =
                    ((((size_t)(b * NH + h)) << 10 | (size_t)l) << 6) | (size_t)d;
                float* dst = (sec == 0) ? g_q : (sec == 1) ? g_k : g_v;
                dst[idx] = val;
            } else {
                C[(size_t)r * N + c] = val;
            }
        }
    }
}

// ---------------------------------------------------------------------------
// RoPE in-place on g_q, g_k. One thread per (token, head, d<32).
// ---------------------------------------------------------------------------
__global__ void rope_kernel(const float* __restrict__ cosT,
                            const float* __restrict__ sinT)
{
    const int idx = blockIdx.x * blockDim.x + threadIdx.x;
    if (idx >= TT * NH * 32) return;
    const int d = idx & 31;
    const int h = (idx >> 5) & (NH - 1);
    const int t = idx >> 9;
    const float c = cosT[t * HD + d];
    const float s = sinT[t * HD + d];
    const int b = t >> 10;
    const int l = t & (L_ - 1);
    const size_t base = (((size_t)(b * NH + h)) << 10 | (size_t)l) << 6;

    const float q1 = g_q[base + d], q2 = g_q[base + d + 32];
    g_q[base + d]      = q1 * c - q2 * s;
    g_q[base + d + 32] = q2 * c + q1 * s;
    const float k1 = g_k[base + d], k2 = g_k[base + d + 32];
    g_k[base + d]      = k1 * c - k2 * s;
    g_k[base + d + 32] = k2 * c + k1 * s;
}

// ---------------------------------------------------------------------------
// Flash attention, fp32. One query row per thread (q + acc in registers),
// K/V tiles (64x64) in smem, broadcast LDS reads. Online softmax per 16-chunk.
// ---------------------------------------------------------------------------
__global__ __launch_bounds__(128) void flash_kernel()
{
    __shared__ float Ks[64][64];
    __shared__ float Vs[64][64];

    const int b = blockIdx.z;
    const int h = blockIdx.y;
    const int tid = threadIdx.x;
    const int l = blockIdx.x * 128 + tid;
    const size_t hb = ((size_t)(b * NH + h)) << 16;  // *(L_*HD)

    const float* qptr = g_q + hb + ((size_t)l << 6);
    float qreg[64];
#pragma unroll
    for (int i = 0; i < 16; i++) {
        float4 v4 = *(const float4*)(qptr + i * 4);
        qreg[i * 4 + 0] = v4.x * 0.125f;   // scale = 1/sqrt(64)
        qreg[i * 4 + 1] = v4.y * 0.125f;
        qreg[i * 4 + 2] = v4.z * 0.125f;
        qreg[i * 4 + 3] = v4.w * 0.125f;
    }

    float m = -1e30f, lsum = 0.f;
    float oacc[64];
#pragma unroll
    for (int d = 0; d < 64; d++) oacc[d] = 0.f;

    const float* kb = g_k + hb;
    const float* vb = g_v + hb;

    for (int kv0 = 0; kv0 < L_; kv0 += 64) {
        __syncthreads();
#pragma unroll
        for (int i = 0; i < 8; i++) {
            const int idx = tid + i * 128;     // 0..1023 float4-index
            const int rr = idx >> 4;
            const int cc = (idx & 15) << 2;
            *(float4*)&Ks[rr][cc] =
                *(const float4*)(kb + ((size_t)(kv0 + rr) << 6) + cc);
            *(float4*)&Vs[rr][cc] =
                *(const float4*)(vb + ((size_t)(kv0 + rr) << 6) + cc);
        }
        __syncthreads();

        for (int j0 = 0; j0 < 64; j0 += 16) {
            float s[16];
#pragma unroll
            for (int j = 0; j < 16; j++) {
                float a0 = 0.f, a1 = 0.f, a2 = 0.f, a3 = 0.f;
#pragma unroll
                for (int d = 0; d < 64; d += 4) {
                    float4 k4 = *(const float4*)&Ks[j0 + j][d];
                    a0 = fmaf(qreg[d + 0], k4.x, a0);
                    a1 = fmaf(qreg[d + 1], k4.y, a1);
                    a2 = fmaf(qreg[d + 2], k4.z, a2);
                    a3 = fmaf(qreg[d + 3], k4.w, a3);
                }
                s[j] = (a0 + a1) + (a2 + a3);
            }
            float mt = s[0];
#pragma unroll
            for (int j = 1; j < 16; j++) mt = fmaxf(mt, s[j]);
            const float mnew = fmaxf(m, mt);
            const float scl = __expf(m - mnew);
            m = mnew;
            lsum *= scl;
#pragma unroll
            for (int d = 0; d < 64; d++) oacc[d] *= scl;
#pragma unroll
            for (int j = 0; j < 16; j++) {
                const float p = __expf(s[j] - mnew);
                lsum += p;
#pragma unroll
                for (int d = 0; d < 64; d += 4) {
                    float4 v4 = *(const float4*)&Vs[j0 + j][d];
                    oacc[d + 0] = fmaf(p, v4.x, oacc[d + 0]);
                    oacc[d + 1] = fmaf(p, v4.y, oacc[d + 1]);
                    oacc[d + 2] = fmaf(p, v4.z, oacc[d + 2]);
                    oacc[d + 3] = fmaf(p, v4.w, oacc[d + 3]);
                }
            }
        }
    }

    const float inv = 1.f / lsum;
    float* optr = g_att + ((size_t)(b * L_ + l)) * DIM + h * HD;
#pragma unroll
    for (int d = 0; d < 64; d += 4) {
        float4 o;
        o.x = oacc[d + 0] * inv;
        o.y = oacc[d + 1] * inv;
        o.z = oacc[d + 2] * inv;
        o.w = oacc[d + 3] * inv;
        *(float4*)(optr + d) = o;
    }
}

// ---------------------------------------------------------------------------
extern "C" void kernel_launch(void* const* d_in, const int* in_sizes, int n_in,
                              void* d_out, int out_size)
{
    (void)in_sizes; (void)n_in; (void)out_size;
    const float* hidden = (const float*)d_in[0];
    const float* cosT   = (const float*)d_in[1];
    const float* sinT   = (const float*)d_in[2];
    const float* w_qkv  = (const float*)d_in[3];
    const float* b_qkv  = (const float*)d_in[4];
    const float* w_proj = (const float*)d_in[5];
    const float* b_proj = (const float*)d_in[6];
    float* out = (float*)d_out;

    float* attp = nullptr;
    cudaGetSymbolAddress((void**)&attp, g_att);

    // 1) QKV GEMM + bias, scattered into g_q/g_k/g_v
    dim3 g1(3 * DIM / 128, TT / 128);
    sgemm_kernel<1><<<g1, 256>>>(hidden, w_qkv, b_qkv, nullptr, TT, 3 * DIM, DIM);

    // 2) RoPE in-place on q, k
    const int nrope = TT * NH * 32;
    rope_kernel<<<(nrope + 255) / 256, 256>>>(cosT, sinT);

    // 3) Flash attention -> g_att [T, DIM]
    flash_kernel<<<dim3(L_ / 128, NH, B_), 128>>>();

    // 4) Output projection -> d_out
    dim3 g2(DIM / 128, TT / 128);
    sgemm_kernel<0><<<g2, 256>>>(attp, w_proj, b_proj, out, TT, DIM, DIM);
}

// round 6
// speedup vs baseline: 1.6814x; 1.6814x over previous
#include <cuda_runtime.h>
#include <cuda_bf16.h>
#include <cstdint>

#define TT   8192
#define DIM  1024
#define NH   16
#define HD   64
#define B_   8
#define L_   1024

// ---------------------------------------------------------------------------
// scratch (allocation-free device globals)
// ---------------------------------------------------------------------------
__device__ float g_q[TT * DIM];
__device__ float g_k[TT * DIM];
__device__ float g_v[TT * DIM];
__device__ __nv_bfloat16 g_Ah[TT * DIM];
__device__ __nv_bfloat16 g_Al[TT * DIM];
__device__ __nv_bfloat16 g_Wqh[3 * DIM * DIM];
__device__ __nv_bfloat16 g_Wql[3 * DIM * DIM];
__device__ __nv_bfloat16 g_Wph[DIM * DIM];
__device__ __nv_bfloat16 g_Wpl[DIM * DIM];
__device__ __nv_bfloat16 g_atth[TT * DIM];
__device__ __nv_bfloat16 g_attl[TT * DIM];

// ---------------------------------------------------------------------------
// family-generic PTX helpers (valid on compute_103 baseline)
// ---------------------------------------------------------------------------
__device__ __forceinline__ uint32_t smem_to_u32(const void* p) {
    uint32_t a;
    asm("{ .reg .u64 t; cvta.to.shared.u64 t, %1; cvt.u32.u64 %0, t; }"
        : "=r"(a) : "l"(p));
    return a;
}
__device__ __forceinline__ void cp16(uint32_t s, const void* g) {
    asm volatile("cp.async.cg.shared.global [%0], [%1], 16;" :: "r"(s), "l"(g));
}
__device__ __forceinline__ void ldmx4(uint32_t* r, uint32_t a) {
    asm volatile("ldmatrix.sync.aligned.m8n8.x4.shared.b16 {%0,%1,%2,%3}, [%4];"
        : "=r"(r[0]), "=r"(r[1]), "=r"(r[2]), "=r"(r[3]) : "r"(a));
}
__device__ __forceinline__ void mma16816(float* c, const uint32_t* a,
                                         uint32_t b0, uint32_t b1) {
    asm volatile("mma.sync.aligned.m16n8k16.row.col.f32.bf16.bf16.f32 "
        "{%0,%1,%2,%3}, {%4,%5,%6,%7}, {%8,%9}, {%0,%1,%2,%3};"
        : "+f"(c[0]), "+f"(c[1]), "+f"(c[2]), "+f"(c[3])
        : "r"(a[0]), "r"(a[1]), "r"(a[2]), "r"(a[3]), "r"(b0), "r"(b1));
}

__device__ __forceinline__ void split2(float x, __nv_bfloat16& h, __nv_bfloat16& l) {
    h = __float2bfloat16(x);
    l = __float2bfloat16(x - __bfloat162float(h));
}

// ---------------------------------------------------------------------------
// elementwise fp32 -> bf16 hi/lo split (for hidden_states)
// ---------------------------------------------------------------------------
__global__ void split_kernel(const float4* __restrict__ X,
                             uint2* __restrict__ H, uint2* __restrict__ L, int n4)
{
    int i = blockIdx.x * blockDim.x + threadIdx.x;
    if (i >= n4) return;
    float4 v = X[i];
    union { __nv_bfloat16 b[4]; uint2 u; } hv, lv;
    split2(v.x, hv.b[0], lv.b[0]);
    split2(v.y, hv.b[1], lv.b[1]);
    split2(v.z, hv.b[2], lv.b[2]);
    split2(v.w, hv.b[3], lv.b[3]);
    H[i] = hv.u;
    L[i] = lv.u;
}

// ---------------------------------------------------------------------------
// W [K,N] fp32 -> W^T [N,K] bf16 hi/lo (tiled transpose)
// ---------------------------------------------------------------------------
__global__ void transpose_split_kernel(const float* __restrict__ W,
    __nv_bfloat16* __restrict__ Th, __nv_bfloat16* __restrict__ Tl, int K, int N)
{
    __shared__ float tile[32][33];
    const int n0 = blockIdx.x * 32, k0 = blockIdx.y * 32;
    const int tx = threadIdx.x, ty = threadIdx.y;
#pragma unroll
    for (int i = 0; i < 32; i += 8)
        tile[ty + i][tx] = W[(size_t)(k0 + ty + i) * N + n0 + tx];
    __syncthreads();
#pragma unroll
    for (int i = 0; i < 32; i += 8) {
        float x = tile[tx][ty + i];
        __nv_bfloat16 h, l;
        split2(x, h, l);
        size_t o = (size_t)(n0 + ty + i) * K + k0 + tx;
        Th[o] = h;
        Tl[o] = l;
    }
}

// ---------------------------------------------------------------------------
// mma.sync bf16 GEMM:  C[M,N] = A[M,K] @ B^T + bias  (B given as [N,K])
// A,B supplied as bf16 hi/lo; 3-term split (hh + hl + lh) in fp32 acc.
// CTA 128x128x32, 8 warps (4x2), warp tile 32x64, cp.async double buffer.
// SMEM layout per tile: row-major [128][32] bf16 (64B rows), 16B chunk
// swizzle: chunk' = chunk ^ ((row>>1)&3)  -> conflict-free stores + ldmatrix.
// SCATTER=1: scatter into g_q/g_k/g_v ([B,H,L,D]). SCATTER=0: write C.
// ---------------------------------------------------------------------------
#define BK 32
#define TILE_BYTES 8192          // 128 rows * 64 B
#define STAGE_BYTES (4 * TILE_BYTES)
#define GEMM_SMEM (2 * STAGE_BYTES)

template <int SCATTER>
__global__ __launch_bounds__(256) void gemm_mma(
    const __nv_bfloat16* __restrict__ Ah, const __nv_bfloat16* __restrict__ Al,
    const __nv_bfloat16* __restrict__ Bh, const __nv_bfloat16* __restrict__ Bl,
    const float* __restrict__ bias, float* __restrict__ C, int N, int K)
{
    extern __shared__ char smem[];
    const uint32_t sbase = smem_to_u32(smem);
    const int tid = threadIdx.x;
    const int lane = tid & 31, warp = tid >> 5;
    const int wm = warp >> 1, wn = warp & 1;          // 4 x 2 warp grid
    const int rowBase = blockIdx.y * 128;
    const int colBase = blockIdx.x * 128;

    float acc[2][8][4];
#pragma unroll
    for (int i = 0; i < 2; i++)
#pragma unroll
        for (int j = 0; j < 8; j++)
#pragma unroll
            for (int q = 0; q < 4; q++) acc[i][j][q] = 0.f;

    const int nC = K / BK;

    // ---- stage loader ----
    auto load_stage = [&](int kc, int s) {
        const int koff = kc * BK;
        const uint32_t st = sbase + s * STAGE_BYTES;
#pragma unroll
        for (int t = 0; t < 4; t++) {
            const __nv_bfloat16* src = (t == 0) ? Ah : (t == 1) ? Al
                                     : (t == 2) ? Bh : Bl;
            const int rb = (t < 2) ? rowBase : colBase;
            const uint32_t tb = st + t * TILE_BYTES;
#pragma unroll
            for (int i = 0; i < 2; i++) {
                const int u = tid + i * 256;          // 0..511
                const int row = u >> 2;
                const int ch = u & 3;
                const __nv_bfloat16* g = src + (size_t)(rb + row) * K + koff + ch * 8;
                const uint32_t sa = tb + row * 64 + ((ch ^ ((row >> 1) & 3)) << 4);
                cp16(sa, g);
            }
        }
        asm volatile("cp.async.commit_group;" ::: "memory");
    };

    load_stage(0, 0);

    for (int kc = 0; kc < nC; kc++) {
        const int cur = kc & 1;
        if (kc + 1 < nC) {
            load_stage(kc + 1, cur ^ 1);
            asm volatile("cp.async.wait_group 1;" ::: "memory");
        } else {
            asm volatile("cp.async.wait_group 0;" ::: "memory");
        }
        __syncthreads();

        const uint32_t st = sbase + cur * STAGE_BYTES;
#pragma unroll
        for (int kst = 0; kst < 2; kst++) {
            uint32_t ahf[2][4], alf[2][4], bhf[4][4], blf[4][4];
#pragma unroll
            for (int mi = 0; mi < 2; mi++) {
                const int row = wm * 32 + mi * 16 + (lane & 15);
                const int ch = kst * 2 + (lane >> 4);
                const uint32_t off = row * 64 + ((ch ^ ((row >> 1) & 3)) << 4);
                ldmx4(ahf[mi], st + 0 * TILE_BYTES + off);
                ldmx4(alf[mi], st + 1 * TILE_BYTES + off);
            }
#pragma unroll
            for (int ng = 0; ng < 4; ng++) {
                const int row = wn * 64 + ng * 16 + (lane & 15);
                const int ch = kst * 2 + (lane >> 4);
                const uint32_t off = row * 64 + ((ch ^ ((row >> 1) & 3)) << 4);
                ldmx4(bhf[ng], st + 2 * TILE_BYTES + off);
                ldmx4(blf[ng], st + 3 * TILE_BYTES + off);
            }
#pragma unroll
            for (int mi = 0; mi < 2; mi++)
#pragma unroll
                for (int ng = 0; ng < 4; ng++)
#pragma unroll
                    for (int sx = 0; sx < 2; sx++) {
                        float* c = acc[mi][ng * 2 + sx];
                        mma16816(c, ahf[mi], bhf[ng][sx], bhf[ng][sx + 2]);
                        mma16816(c, ahf[mi], blf[ng][sx], blf[ng][sx + 2]);
                        mma16816(c, alf[mi], bhf[ng][sx], bhf[ng][sx + 2]);
                    }
        }
        __syncthreads();
    }

    // ---- epilogue: bias + store (acc frag: c0,c1=(r,c/c+1), c2,c3=(r+8,*)) ----
#pragma unroll
    for (int mi = 0; mi < 2; mi++) {
        const int r0 = rowBase + wm * 32 + mi * 16 + (lane >> 2);
#pragma unroll
        for (int ni = 0; ni < 8; ni++) {
            const int c = colBase + wn * 64 + ni * 8 + (lane & 3) * 2;
            const float2 bv = *(const float2*)(bias + c);
            float2 v0 = { acc[mi][ni][0] + bv.x, acc[mi][ni][1] + bv.y };
            float2 v1 = { acc[mi][ni][2] + bv.x, acc[mi][ni][3] + bv.y };
            if (SCATTER) {
                const int sec = c >> 10;
                const int h = (c >> 6) & (NH - 1);
                const int d = c & (HD - 1);
                float* dst = (sec == 0) ? g_q : (sec == 1) ? g_k : g_v;
                {
                    const int b = r0 >> 10, l = r0 & (L_ - 1);
                    const size_t idx = (((size_t)(b * NH + h)) << 16) + ((size_t)l << 6) + d;
                    *(float2*)(dst + idx) = v0;
                }
                {
                    const int r1 = r0 + 8;
                    const int b = r1 >> 10, l = r1 & (L_ - 1);
                    const size_t idx = (((size_t)(b * NH + h)) << 16) + ((size_t)l << 6) + d;
                    *(float2*)(dst + idx) = v1;
                }
            } else {
                *(float2*)(C + (size_t)r0 * N + c) = v0;
                *(float2*)(C + (size_t)(r0 + 8) * N + c) = v1;
            }
        }
    }
}

// ---------------------------------------------------------------------------
// RoPE in-place on g_q, g_k.
// ---------------------------------------------------------------------------
__global__ void rope_kernel(const float* __restrict__ cosT,
                            const float* __restrict__ sinT)
{
    const int idx = blockIdx.x * blockDim.x + threadIdx.x;
    if (idx >= TT * NH * 32) return;
    const int d = idx & 31;
    const int h = (idx >> 5) & (NH - 1);
    const int t = idx >> 9;
    const float c = cosT[t * HD + d];
    const float s = sinT[t * HD + d];
    const int b = t >> 10;
    const int l = t & (L_ - 1);
    const size_t base = (((size_t)(b * NH + h)) << 16) + ((size_t)l << 6);

    const float q1 = g_q[base + d], q2 = g_q[base + d + 32];
    g_q[base + d]      = q1 * c - q2 * s;
    g_q[base + d + 32] = q2 * c + q1 * s;
    const float k1 = g_k[base + d], k2 = g_k[base + d + 32];
    g_k[base + d]      = k1 * c - k2 * s;
    g_k[base + d + 32] = k2 * c + k1 * s;
}

// ---------------------------------------------------------------------------
// Flash attention fp32; outputs bf16 hi/lo directly (input to proj GEMM).
// ---------------------------------------------------------------------------
__global__ __launch_bounds__(128) void flash_kernel()
{
    __shared__ float Ks[64][64];
    __shared__ float Vs[64][64];

    const int b = blockIdx.z;
    const int h = blockIdx.y;
    const int tid = threadIdx.x;
    const int l = blockIdx.x * 128 + tid;
    const size_t hb = ((size_t)(b * NH + h)) << 16;

    const float* qptr = g_q + hb + ((size_t)l << 6);
    float qreg[64];
#pragma unroll
    for (int i = 0; i < 16; i++) {
        float4 v4 = *(const float4*)(qptr + i * 4);
        qreg[i * 4 + 0] = v4.x * 0.125f;
        qreg[i * 4 + 1] = v4.y * 0.125f;
        qreg[i * 4 + 2] = v4.z * 0.125f;
        qreg[i * 4 + 3] = v4.w * 0.125f;
    }

    float m = -1e30f, lsum = 0.f;
    float oacc[64];
#pragma unroll
    for (int d = 0; d < 64; d++) oacc[d] = 0.f;

    const float* kb = g_k + hb;
    const float* vb = g_v + hb;

    for (int kv0 = 0; kv0 < L_; kv0 += 64) {
        __syncthreads();
#pragma unroll
        for (int i = 0; i < 8; i++) {
            const int idx = tid + i * 128;
            const int rr = idx >> 4;
            const int cc = (idx & 15) << 2;
            *(float4*)&Ks[rr][cc] = *(const float4*)(kb + ((size_t)(kv0 + rr) << 6) + cc);
            *(float4*)&Vs[rr][cc] = *(const float4*)(vb + ((size_t)(kv0 + rr) << 6) + cc);
        }
        __syncthreads();

        for (int j0 = 0; j0 < 64; j0 += 16) {
            float s[16];
#pragma unroll
            for (int j = 0; j < 16; j++) {
                float a0 = 0.f, a1 = 0.f, a2 = 0.f, a3 = 0.f;
#pragma unroll
                for (int d = 0; d < 64; d += 4) {
                    float4 k4 = *(const float4*)&Ks[j0 + j][d];
                    a0 = fmaf(qreg[d + 0], k4.x, a0);
                    a1 = fmaf(qreg[d + 1], k4.y, a1);
                    a2 = fmaf(qreg[d + 2], k4.z, a2);
                    a3 = fmaf(qreg[d + 3], k4.w, a3);
                }
                s[j] = (a0 + a1) + (a2 + a3);
            }
            float mt = s[0];
#pragma unroll
            for (int j = 1; j < 16; j++) mt = fmaxf(mt, s[j]);
            const float mnew = fmaxf(m, mt);
            const float scl = __expf(m - mnew);
            m = mnew;
            lsum *= scl;
#pragma unroll
            for (int d = 0; d < 64; d++) oacc[d] *= scl;
#pragma unroll
            for (int j = 0; j < 16; j++) {
                const float p = __expf(s[j] - mnew);
                lsum += p;
#pragma unroll
                for (int d = 0; d < 64; d += 4) {
                    float4 v4 = *(const float4*)&Vs[j0 + j][d];
                    oacc[d + 0] = fmaf(p, v4.x, oacc[d + 0]);
                    oacc[d + 1] = fmaf(p, v4.y, oacc[d + 1]);
                    oacc[d + 2] = fmaf(p, v4.z, oacc[d + 2]);
                    oacc[d + 3] = fmaf(p, v4.w, oacc[d + 3]);
                }
            }
        }
    }

    const float inv = 1.f / lsum;
    __nv_bfloat16* oph = g_atth + ((size_t)(b * L_ + l)) * DIM + h * HD;
    __nv_bfloat16* opl = g_attl + ((size_t)(b * L_ + l)) * DIM + h * HD;
#pragma unroll
    for (int d = 0; d < 64; d += 8) {
        union { __nv_bfloat16 bb[8]; uint4 u; } hv, lv;
#pragma unroll
        for (int j = 0; j < 8; j++) split2(oacc[d + j] * inv, hv.bb[j], lv.bb[j]);
        *(uint4*)(oph + d) = hv.u;
        *(uint4*)(opl + d) = lv.u;
    }
}

// ---------------------------------------------------------------------------
extern "C" void kernel_launch(void* const* d_in, const int* in_sizes, int n_in,
                              void* d_out, int out_size)
{
    (void)in_sizes; (void)n_in; (void)out_size;
    const float* hidden = (const float*)d_in[0];
    const float* cosT   = (const float*)d_in[1];
    const float* sinT   = (const float*)d_in[2];
    const float* w_qkv  = (const float*)d_in[3];
    const float* b_qkv  = (const float*)d_in[4];
    const float* w_proj = (const float*)d_in[5];
    const float* b_proj = (const float*)d_in[6];
    float* out = (float*)d_out;

    __nv_bfloat16 *ah, *al, *wqh, *wql, *wph, *wpl, *ath, *atl;
    cudaGetSymbolAddress((void**)&ah,  g_Ah);
    cudaGetSymbolAddress((void**)&al,  g_Al);
    cudaGetSymbolAddress((void**)&wqh, g_Wqh);
    cudaGetSymbolAddress((void**)&wql, g_Wql);
    cudaGetSymbolAddress((void**)&wph, g_Wph);
    cudaGetSymbolAddress((void**)&wpl, g_Wpl);
    cudaGetSymbolAddress((void**)&ath, g_atth);
    cudaGetSymbolAddress((void**)&atl, g_attl);

    cudaFuncSetAttribute(gemm_mma<1>, cudaFuncAttributeMaxDynamicSharedMemorySize, GEMM_SMEM);
    cudaFuncSetAttribute(gemm_mma<0>, cudaFuncAttributeMaxDynamicSharedMemorySize, GEMM_SMEM);

    // 1) split hidden_states into bf16 hi/lo
    const int n4 = TT * DIM / 4;
    split_kernel<<<(n4 + 255) / 256, 256>>>((const float4*)hidden, (uint2*)ah, (uint2*)al, n4);

    // 2) transpose+split weights
    transpose_split_kernel<<<dim3(3 * DIM / 32, DIM / 32), dim3(32, 8)>>>(w_qkv, wqh, wql, DIM, 3 * DIM);
    transpose_split_kernel<<<dim3(DIM / 32, DIM / 32), dim3(32, 8)>>>(w_proj, wph, wpl, DIM, DIM);

    // 3) QKV GEMM (mma.sync bf16) with scatter into g_q/g_k/g_v
    gemm_mma<1><<<dim3(3 * DIM / 128, TT / 128), 256, GEMM_SMEM>>>(
        ah, al, wqh, wql, b_qkv, nullptr, 3 * DIM, DIM);

    // 4) RoPE in-place
    const int nrope = TT * NH * 32;
    rope_kernel<<<(nrope + 255) / 256, 256>>>(cosT, sinT);

    // 5) Flash attention -> bf16 hi/lo att output
    flash_kernel<<<dim3(L_ / 128, NH, B_), 128>>>();

    // 6) Output projection (mma.sync bf16) -> d_out
    gemm_mma<0><<<dim3(DIM / 128, TT / 128), 256, GEMM_SMEM>>>(
        ath, atl, wph, wpl, b_proj, out, DIM, DIM);
}

// round 7
// speedup vs baseline: 3.4128x; 2.0297x over previous
#include <cuda_runtime.h>
#include <cuda_bf16.h>
#include <cstdint>

#define TT   8192
#define DIM  1024
#define NH   16
#define HD   64
#define B_   8
#define L_   1024

// ---------------------------------------------------------------------------
// scratch (allocation-free device globals)
// ---------------------------------------------------------------------------
__device__ float g_q[TT * DIM];                 // fp32 q pre-rope [B,H,L,D]
__device__ float g_k[TT * DIM];                 // fp32 k pre-rope [B,H,L,D]
__device__ __nv_bfloat16 g_qh[TT * DIM];        // post-rope, scaled, hi/lo
__device__ __nv_bfloat16 g_ql[TT * DIM];
__device__ __nv_bfloat16 g_kh[TT * DIM];
__device__ __nv_bfloat16 g_kl[TT * DIM];
__device__ __nv_bfloat16 g_vh[TT * DIM];
__device__ __nv_bfloat16 g_vl[TT * DIM];
__device__ __nv_bfloat16 g_Ah[TT * DIM];
__device__ __nv_bfloat16 g_Al[TT * DIM];
__device__ __nv_bfloat16 g_Wqh[3 * DIM * DIM];
__device__ __nv_bfloat16 g_Wql[3 * DIM * DIM];
__device__ __nv_bfloat16 g_Wph[DIM * DIM];
__device__ __nv_bfloat16 g_Wpl[DIM * DIM];
__device__ __nv_bfloat16 g_atth[TT * DIM];
__device__ __nv_bfloat16 g_attl[TT * DIM];

// ---------------------------------------------------------------------------
// family-generic PTX helpers
// ---------------------------------------------------------------------------
__device__ __forceinline__ uint32_t smem_to_u32(const void* p) {
    uint32_t a;
    asm("{ .reg .u64 t; cvta.to.shared.u64 t, %1; cvt.u32.u64 %0, t; }"
        : "=r"(a) : "l"(p));
    return a;
}
__device__ __forceinline__ void cp16(uint32_t s, const void* g) {
    asm volatile("cp.async.cg.shared.global [%0], [%1], 16;" :: "r"(s), "l"(g));
}
__device__ __forceinline__ void ldmx4(uint32_t* r, uint32_t a) {
    asm volatile("ldmatrix.sync.aligned.m8n8.x4.shared.b16 {%0,%1,%2,%3}, [%4];"
        : "=r"(r[0]), "=r"(r[1]), "=r"(r[2]), "=r"(r[3]) : "r"(a));
}
__device__ __forceinline__ void ldmx4t(uint32_t* r, uint32_t a) {
    asm volatile("ldmatrix.sync.aligned.m8n8.x4.trans.shared.b16 {%0,%1,%2,%3}, [%4];"
        : "=r"(r[0]), "=r"(r[1]), "=r"(r[2]), "=r"(r[3]) : "r"(a));
}
__device__ __forceinline__ void mma16816(float* c, const uint32_t* a,
                                         uint32_t b0, uint32_t b1) {
    asm volatile("mma.sync.aligned.m16n8k16.row.col.f32.bf16.bf16.f32 "
        "{%0,%1,%2,%3}, {%4,%5,%6,%7}, {%8,%9}, {%0,%1,%2,%3};"
        : "+f"(c[0]), "+f"(c[1]), "+f"(c[2]), "+f"(c[3])
        : "r"(a[0]), "r"(a[1]), "r"(a[2]), "r"(a[3]), "r"(b0), "r"(b1));
}
__device__ __forceinline__ void split2(float x, __nv_bfloat16& h, __nv_bfloat16& l) {
    h = __float2bfloat16(x);
    l = __float2bfloat16(x - __bfloat162float(h));
}
__device__ __forceinline__ uint32_t pack2(float a, float b) {
    __nv_bfloat162 t = __floats2bfloat162_rn(a, b);
    return *(uint32_t*)&t;
}

// ---------------------------------------------------------------------------
// elementwise fp32 -> bf16 hi/lo split (for hidden_states)
// ---------------------------------------------------------------------------
__global__ void split_kernel(const float4* __restrict__ X,
                             uint2* __restrict__ H, uint2* __restrict__ L, int n4)
{
    int i = blockIdx.x * blockDim.x + threadIdx.x;
    if (i >= n4) return;
    float4 v = X[i];
    union { __nv_bfloat16 b[4]; uint2 u; } hv, lv;
    split2(v.x, hv.b[0], lv.b[0]);
    split2(v.y, hv.b[1], lv.b[1]);
    split2(v.z, hv.b[2], lv.b[2]);
    split2(v.w, hv.b[3], lv.b[3]);
    H[i] = hv.u;
    L[i] = lv.u;
}

// ---------------------------------------------------------------------------
// W [K,N] fp32 -> W^T [N,K] bf16 hi/lo (tiled transpose)
// ---------------------------------------------------------------------------
__global__ void transpose_split_kernel(const float* __restrict__ W,
    __nv_bfloat16* __restrict__ Th, __nv_bfloat16* __restrict__ Tl, int K, int N)
{
    __shared__ float tile[32][33];
    const int n0 = blockIdx.x * 32, k0 = blockIdx.y * 32;
    const int tx = threadIdx.x, ty = threadIdx.y;
#pragma unroll
    for (int i = 0; i < 32; i += 8)
        tile[ty + i][tx] = W[(size_t)(k0 + ty + i) * N + n0 + tx];
    __syncthreads();
#pragma unroll
    for (int i = 0; i < 32; i += 8) {
        float x = tile[tx][ty + i];
        __nv_bfloat16 h, l;
        split2(x, h, l);
        size_t o = (size_t)(n0 + ty + i) * K + k0 + tx;
        Th[o] = h;
        Tl[o] = l;
    }
}

// ---------------------------------------------------------------------------
// mma.sync bf16 GEMM (same as R4/R5, plus minctapersm=2)
// SCATTER=1: q,k fp32 to g_q/g_k; v bf16 hi/lo to g_vh/g_vl.
// ---------------------------------------------------------------------------
#define BK 32
#define TILE_BYTES 8192
#define STAGE_BYTES (4 * TILE_BYTES)
#define GEMM_SMEM (2 * STAGE_BYTES)

template <int SCATTER>
__global__ __launch_bounds__(256, 2) void gemm_mma(
    const __nv_bfloat16* __restrict__ Ah, const __nv_bfloat16* __restrict__ Al,
    const __nv_bfloat16* __restrict__ Bh, const __nv_bfloat16* __restrict__ Bl,
    const float* __restrict__ bias, float* __restrict__ C, int N, int K)
{
    extern __shared__ char smem[];
    const uint32_t sbase = smem_to_u32(smem);
    const int tid = threadIdx.x;
    const int lane = tid & 31, warp = tid >> 5;
    const int wm = warp >> 1, wn = warp & 1;
    const int rowBase = blockIdx.y * 128;
    const int colBase = blockIdx.x * 128;

    float acc[2][8][4];
#pragma unroll
    for (int i = 0; i < 2; i++)
#pragma unroll
        for (int j = 0; j < 8; j++)
#pragma unroll
            for (int q = 0; q < 4; q++) acc[i][j][q] = 0.f;

    const int nC = K / BK;

    auto load_stage = [&](int kc, int s) {
        const int koff = kc * BK;
        const uint32_t st = sbase + s * STAGE_BYTES;
#pragma unroll
        for (int t = 0; t < 4; t++) {
            const __nv_bfloat16* src = (t == 0) ? Ah : (t == 1) ? Al
                                     : (t == 2) ? Bh : Bl;
            const int rb = (t < 2) ? rowBase : colBase;
            const uint32_t tb = st + t * TILE_BYTES;
#pragma unroll
            for (int i = 0; i < 2; i++) {
                const int u = tid + i * 256;
                const int row = u >> 2;
                const int ch = u & 3;
                const __nv_bfloat16* g = src + (size_t)(rb + row) * K + koff + ch * 8;
                const uint32_t sa = tb + row * 64 + ((ch ^ ((row >> 1) & 3)) << 4);
                cp16(sa, g);
            }
        }
        asm volatile("cp.async.commit_group;" ::: "memory");
    };

    load_stage(0, 0);

    for (int kc = 0; kc < nC; kc++) {
        const int cur = kc & 1;
        if (kc + 1 < nC) {
            load_stage(kc + 1, cur ^ 1);
            asm volatile("cp.async.wait_group 1;" ::: "memory");
        } else {
            asm volatile("cp.async.wait_group 0;" ::: "memory");
        }
        __syncthreads();

        const uint32_t st = sbase + cur * STAGE_BYTES;
#pragma unroll
        for (int kst = 0; kst < 2; kst++) {
            uint32_t ahf[2][4], alf[2][4], bhf[4][4], blf[4][4];
#pragma unroll
            for (int mi = 0; mi < 2; mi++) {
                const int row = wm * 32 + mi * 16 + (lane & 15);
                const int ch = kst * 2 + (lane >> 4);
                const uint32_t off = row * 64 + ((ch ^ ((row >> 1) & 3)) << 4);
                ldmx4(ahf[mi], st + 0 * TILE_BYTES + off);
                ldmx4(alf[mi], st + 1 * TILE_BYTES + off);
            }
#pragma unroll
            for (int ng = 0; ng < 4; ng++) {
                const int row = wn * 64 + ng * 16 + (lane & 15);
                const int ch = kst * 2 + (lane >> 4);
                const uint32_t off = row * 64 + ((ch ^ ((row >> 1) & 3)) << 4);
                ldmx4(bhf[ng], st + 2 * TILE_BYTES + off);
                ldmx4(blf[ng], st + 3 * TILE_BYTES + off);
            }
#pragma unroll
            for (int mi = 0; mi < 2; mi++)
#pragma unroll
                for (int ng = 0; ng < 4; ng++)
#pragma unroll
                    for (int sx = 0; sx < 2; sx++) {
                        float* c = acc[mi][ng * 2 + sx];
                        mma16816(c, ahf[mi], bhf[ng][sx], bhf[ng][sx + 2]);
                        mma16816(c, ahf[mi], blf[ng][sx], blf[ng][sx + 2]);
                        mma16816(c, alf[mi], bhf[ng][sx], bhf[ng][sx + 2]);
                    }
        }
        __syncthreads();
    }

#pragma unroll
    for (int mi = 0; mi < 2; mi++) {
        const int r0 = rowBase + wm * 32 + mi * 16 + (lane >> 2);
#pragma unroll
        for (int ni = 0; ni < 8; ni++) {
            const int c = colBase + wn * 64 + ni * 8 + (lane & 3) * 2;
            const float2 bv = *(const float2*)(bias + c);
            float2 v0 = { acc[mi][ni][0] + bv.x, acc[mi][ni][1] + bv.y };
            float2 v1 = { acc[mi][ni][2] + bv.x, acc[mi][ni][3] + bv.y };
            if (SCATTER) {
                const int sec = c >> 10;
                const int h = (c >> 6) & (NH - 1);
                const int d = c & (HD - 1);
#pragma unroll
                for (int rr = 0; rr < 2; rr++) {
                    const int r = r0 + rr * 8;
                    const float2 vv = rr ? v1 : v0;
                    const int b = r >> 10, l = r & (L_ - 1);
                    const size_t idx = (((size_t)(b * NH + h)) << 16) + ((size_t)l << 6) + d;
                    if (sec == 2) {
                        __nv_bfloat16 h0, l0, h1, l1;
                        split2(vv.x, h0, l0);
                        split2(vv.y, h1, l1);
                        *(uint32_t*)(g_vh + idx) =
                            (uint32_t)*(uint16_t*)&h0 | ((uint32_t)*(uint16_t*)&h1 << 16);
                        *(uint32_t*)(g_vl + idx) =
                            (uint32_t)*(uint16_t*)&l0 | ((uint32_t)*(uint16_t*)&l1 << 16);
                    } else {
                        float* dst = (sec == 0) ? g_q : g_k;
                        *(float2*)(dst + idx) = vv;
                    }
                }
            } else {
                *(float2*)(C + (size_t)r0 * N + c) = v0;
                *(float2*)(C + (size_t)(r0 + 8) * N + c) = v1;
            }
        }
    }
}

// ---------------------------------------------------------------------------
// RoPE: fp32 q,k -> bf16 hi/lo (q pre-scaled by 1/8). One thread per (t,h,d<32).
// ---------------------------------------------------------------------------
__global__ void rope_split_kernel(const float* __restrict__ cosT,
                                  const float* __restrict__ sinT)
{
    const int idx = blockIdx.x * blockDim.x + threadIdx.x;
    if (idx >= TT * NH * 32) return;
    const int d = idx & 31;
    const int h = (idx >> 5) & (NH - 1);
    const int t = idx >> 9;
    const float c = cosT[t * HD + d];
    const float s = sinT[t * HD + d];
    const int b = t >> 10;
    const int l = t & (L_ - 1);
    const size_t base = (((size_t)(b * NH + h)) << 16) + ((size_t)l << 6);

    const float q1 = g_q[base + d], q2 = g_q[base + d + 32];
    const float qa = (q1 * c - q2 * s) * 0.125f;
    const float qb = (q2 * c + q1 * s) * 0.125f;
    __nv_bfloat16 hh, ll;
    split2(qa, hh, ll); g_qh[base + d] = hh;      g_ql[base + d] = ll;
    split2(qb, hh, ll); g_qh[base + d + 32] = hh; g_ql[base + d + 32] = ll;

    const float k1 = g_k[base + d], k2 = g_k[base + d + 32];
    const float ka = k1 * c - k2 * s;
    const float kb = k2 * c + k1 * s;
    split2(ka, hh, ll); g_kh[base + d] = hh;      g_kl[base + d] = ll;
    split2(kb, hh, ll); g_kh[base + d + 32] = hh; g_kl[base + d + 32] = ll;
}

// ---------------------------------------------------------------------------
// Flash attention on mma.sync bf16 (hi/lo split everywhere).
// CTA: 128 q-rows x one (b,h); 8 warps, warp = 16 q-rows x full 64 kv/d.
// KV tiles 64x64 double-buffered via cp.async. P stays in registers
// (S C-fragment == PV A-fragment layout).
// SMEM: Q hi/lo 2x16KB @0; stages @32768: {Kh,Kl,Vh,Vl} x 8KB, x2 stages.
// Tile rows are 128B (64 bf16); swizzle ch ^= (row&7).
// ---------------------------------------------------------------------------
#define FL_SMEM (32768 + 2 * 32768)

__global__ __launch_bounds__(256) void flash_mma()
{
    extern __shared__ char smem[];
    const uint32_t base = smem_to_u32(smem);
    const int tid = threadIdx.x;
    const int lane = tid & 31, wm = tid >> 5;
    const int b = blockIdx.z, h = blockIdx.y;
    const int q0 = blockIdx.x * 128;
    const size_t hb = ((size_t)(b * NH + h)) << 16;

    // ---- load Q hi/lo (one group) ----
#pragma unroll
    for (int part = 0; part < 2; part++) {
        const __nv_bfloat16* src = (part ? g_ql : g_qh) + hb + (size_t)q0 * HD;
#pragma unroll
        for (int i = 0; i < 4; i++) {
            const int u = tid + i * 256;
            const int row = u >> 3, ch = u & 7;
            cp16(base + part * 16384 + row * 128 + ((ch ^ (row & 7)) << 4),
                 src + row * 64 + ch * 8);
        }
    }
    asm volatile("cp.async.commit_group;" ::: "memory");

    auto load_kv = [&](int t, int s) {
        const uint32_t st = base + 32768 + s * 32768;
#pragma unroll
        for (int tt = 0; tt < 4; tt++) {
            const __nv_bfloat16* src =
                ((tt == 0) ? g_kh : (tt == 1) ? g_kl : (tt == 2) ? g_vh : g_vl)
                + hb + (size_t)t * 64 * 64;
#pragma unroll
            for (int i = 0; i < 2; i++) {
                const int u = tid + i * 256;
                const int row = u >> 3, ch = u & 7;
                cp16(st + tt * 8192 + row * 128 + ((ch ^ (row & 7)) << 4),
                     src + row * 64 + ch * 8);
            }
        }
        asm volatile("cp.async.commit_group;" ::: "memory");
    };

    load_kv(0, 0);
    asm volatile("cp.async.wait_group 1;" ::: "memory");   // Q ready
    __syncthreads();

    // ---- Q fragments into registers ----
    uint32_t qfh[4][4], qfl[4][4];
#pragma unroll
    for (int kst = 0; kst < 4; kst++) {
        const int row = wm * 16 + (lane & 15);
        const int ch = kst * 2 + (lane >> 4);
        const uint32_t off = row * 128 + ((ch ^ (row & 7)) << 4);
        ldmx4(qfh[kst], base + off);
        ldmx4(qfl[kst], base + 16384 + off);
    }

    float m0 = -1e30f, m1 = -1e30f, l0 = 0.f, l1 = 0.f;
    float o[8][4];
#pragma unroll
    for (int g = 0; g < 8; g++)
#pragma unroll
        for (int q = 0; q < 4; q++) o[g][q] = 0.f;

    const int NT = L_ / 64;     // 16 tiles
    for (int t = 0; t < NT; t++) {
        if (t + 1 < NT) {
            load_kv(t + 1, (t + 1) & 1);
            asm volatile("cp.async.wait_group 1;" ::: "memory");
        } else {
            asm volatile("cp.async.wait_group 0;" ::: "memory");
        }
        __syncthreads();
        const uint32_t st = base + 32768 + (t & 1) * 32768;

        // ---- S = Q K^T (3-term) ----
        float s[8][4];
#pragma unroll
        for (int g = 0; g < 8; g++)
#pragma unroll
            for (int q = 0; q < 4; q++) s[g][q] = 0.f;

#pragma unroll
        for (int kst = 0; kst < 4; kst++) {
            uint32_t kh[4][4], kl[4][4];
#pragma unroll
            for (int ng = 0; ng < 4; ng++) {
                const int row = ng * 16 + (lane & 15);
                const int ch = kst * 2 + (lane >> 4);
                const uint32_t off = row * 128 + ((ch ^ (row & 7)) << 4);
                ldmx4(kh[ng], st + off);
                ldmx4(kl[ng], st + 8192 + off);
            }
#pragma unroll
            for (int ng = 0; ng < 4; ng++)
#pragma unroll
                for (int sx = 0; sx < 2; sx++) {
                    float* c = s[ng * 2 + sx];
                    mma16816(c, qfh[kst], kh[ng][sx], kh[ng][sx + 2]);
                    mma16816(c, qfh[kst], kl[ng][sx], kl[ng][sx + 2]);
                    mma16816(c, qfl[kst], kh[ng][sx], kh[ng][sx + 2]);
                }
        }

        // ---- online softmax (rows r=lane>>2 and r+8; quad = lane&3) ----
        float mt0 = -1e30f, mt1 = -1e30f;
#pragma unroll
        for (int g = 0; g < 8; g++) {
            mt0 = fmaxf(mt0, fmaxf(s[g][0], s[g][1]));
            mt1 = fmaxf(mt1, fmaxf(s[g][2], s[g][3]));
        }
        mt0 = fmaxf(mt0, __shfl_xor_sync(0xffffffff, mt0, 1));
        mt0 = fmaxf(mt0, __shfl_xor_sync(0xffffffff, mt0, 2));
        mt1 = fmaxf(mt1, __shfl_xor_sync(0xffffffff, mt1, 1));
        mt1 = fmaxf(mt1, __shfl_xor_sync(0xffffffff, mt1, 2));
        const float mn0 = fmaxf(m0, mt0);
        const float mn1 = fmaxf(m1, mt1);
        const float sc0 = __expf(m0 - mn0);
        const float sc1 = __expf(m1 - mn1);
        m0 = mn0; m1 = mn1;
        l0 *= sc0; l1 *= sc1;
#pragma unroll
        for (int g = 0; g < 8; g++) {
            o[g][0] *= sc0; o[g][1] *= sc0;
            o[g][2] *= sc1; o[g][3] *= sc1;
        }

        // ---- P = exp(S - m), packed hi/lo A-fragments ----
        uint32_t ph[4][4], pl[4][4];
#pragma unroll
        for (int g = 0; g < 8; g++) {
            const float p0 = __expf(s[g][0] - mn0);
            const float p1 = __expf(s[g][1] - mn0);
            const float p2 = __expf(s[g][2] - mn1);
            const float p3 = __expf(s[g][3] - mn1);
            l0 += p0 + p1;
            l1 += p2 + p3;
            __nv_bfloat16 hh0, ll0, hh1, ll1, hh2, ll2, hh3, ll3;
            split2(p0, hh0, ll0); split2(p1, hh1, ll1);
            split2(p2, hh2, ll2); split2(p3, hh3, ll3);
            const int kg = g >> 1;
            const int a = (g & 1) ? 2 : 0;
            ph[kg][a]     = (uint32_t)*(uint16_t*)&hh0 | ((uint32_t)*(uint16_t*)&hh1 << 16);
            ph[kg][a + 1] = (uint32_t)*(uint16_t*)&hh2 | ((uint32_t)*(uint16_t*)&hh3 << 16);
            pl[kg][a]     = (uint32_t)*(uint16_t*)&ll0 | ((uint32_t)*(uint16_t*)&ll1 << 16);
            pl[kg][a + 1] = (uint32_t)*(uint16_t*)&ll2 | ((uint32_t)*(uint16_t*)&ll3 << 16);
        }

        // ---- O += P V (3-term), V via ldmatrix.trans ----
#pragma unroll
        for (int kg = 0; kg < 4; kg++) {
            uint32_t vh[4][4], vl[4][4];
#pragma unroll
            for (int dp = 0; dp < 4; dp++) {
                const int row = kg * 16 + ((lane >> 4) << 3) + (lane & 7);
                const int ch = dp * 2 + ((lane >> 3) & 1);
                const uint32_t off = row * 128 + ((ch ^ (row & 7)) << 4);
                ldmx4t(vh[dp], st + 16384 + off);
                ldmx4t(vl[dp], st + 24576 + off);
            }
#pragma unroll
            for (int dp = 0; dp < 4; dp++)
#pragma unroll
                for (int sx = 0; sx < 2; sx++) {
                    float* c = o[dp * 2 + sx];
                    mma16816(c, ph[kg], vh[dp][sx], vh[dp][sx + 2]);
                    mma16816(c, ph[kg], vl[dp][sx], vl[dp][sx + 2]);
                    mma16816(c, pl[kg], vh[dp][sx], vh[dp][sx + 2]);
                }
        }
        __syncthreads();
    }

    // ---- normalize + write bf16 hi/lo to [T, DIM] ----
    l0 += __shfl_xor_sync(0xffffffff, l0, 1);
    l0 += __shfl_xor_sync(0xffffffff, l0, 2);
    l1 += __shfl_xor_sync(0xffffffff, l1, 1);
    l1 += __shfl_xor_sync(0xffffffff, l1, 2);
    const float inv0 = 1.f / l0;
    const float inv1 = 1.f / l1;

    const int r0 = q0 + wm * 16 + (lane >> 2);
    const size_t tok0 = (size_t)(b * L_ + r0) * DIM + h * HD;
    const size_t tok1 = tok0 + 8 * DIM;
#pragma unroll
    for (int g = 0; g < 8; g++) {
        const int d = g * 8 + (lane & 3) * 2;
        __nv_bfloat16 h0, lo0, h1, lo1;
        split2(o[g][0] * inv0, h0, lo0);
        split2(o[g][1] * inv0, h1, lo1);
        *(uint32_t*)(g_atth + tok0 + d) =
            (uint32_t)*(uint16_t*)&h0 | ((uint32_t)*(uint16_t*)&h1 << 16);
        *(uint32_t*)(g_attl + tok0 + d) =
            (uint32_t)*(uint16_t*)&lo0 | ((uint32_t)*(uint16_t*)&lo1 << 16);
        split2(o[g][2] * inv1, h0, lo0);
        split2(o[g][3] * inv1, h1, lo1);
        *(uint32_t*)(g_atth + tok1 + d) =
            (uint32_t)*(uint16_t*)&h0 | ((uint32_t)*(uint16_t*)&h1 << 16);
        *(uint32_t*)(g_attl + tok1 + d) =
            (uint32_t)*(uint16_t*)&lo0 | ((uint32_t)*(uint16_t*)&lo1 << 16);
    }
}

// ---------------------------------------------------------------------------
extern "C" void kernel_launch(void* const* d_in, const int* in_sizes, int n_in,
                              void* d_out, int out_size)
{
    (void)in_sizes; (void)n_in; (void)out_size;
    const float* hidden = (const float*)d_in[0];
    const float* cosT   = (const float*)d_in[1];
    const float* sinT   = (const float*)d_in[2];
    const float* w_qkv  = (const float*)d_in[3];
    const float* b_qkv  = (const float*)d_in[4];
    const float* w_proj = (const float*)d_in[5];
    const float* b_proj = (const float*)d_in[6];
    float* out = (float*)d_out;

    __nv_bfloat16 *ah, *al, *wqh, *wql, *wph, *wpl, *ath, *atl;
    cudaGetSymbolAddress((void**)&ah,  g_Ah);
    cudaGetSymbolAddress((void**)&al,  g_Al);
    cudaGetSymbolAddress((void**)&wqh, g_Wqh);
    cudaGetSymbolAddress((void**)&wql, g_Wql);
    cudaGetSymbolAddress((void**)&wph, g_Wph);
    cudaGetSymbolAddress((void**)&wpl, g_Wpl);
    cudaGetSymbolAddress((void**)&ath, g_atth);
    cudaGetSymbolAddress((void**)&atl, g_attl);

    cudaFuncSetAttribute(gemm_mma<1>, cudaFuncAttributeMaxDynamicSharedMemorySize, GEMM_SMEM);
    cudaFuncSetAttribute(gemm_mma<0>, cudaFuncAttributeMaxDynamicSharedMemorySize, GEMM_SMEM);
    cudaFuncSetAttribute(flash_mma, cudaFuncAttributeMaxDynamicSharedMemorySize, FL_SMEM);

    // 1) split hidden_states into bf16 hi/lo
    const int n4 = TT * DIM / 4;
    split_kernel<<<(n4 + 255) / 256, 256>>>((const float4*)hidden, (uint2*)ah, (uint2*)al, n4);

    // 2) transpose+split weights
    transpose_split_kernel<<<dim3(3 * DIM / 32, DIM / 32), dim3(32, 8)>>>(w_qkv, wqh, wql, DIM, 3 * DIM);
    transpose_split_kernel<<<dim3(DIM / 32, DIM / 32), dim3(32, 8)>>>(w_proj, wph, wpl, DIM, DIM);

    // 3) QKV GEMM with scatter (q,k fp32; v bf16 hi/lo)
    gemm_mma<1><<<dim3(3 * DIM / 128, TT / 128), 256, GEMM_SMEM>>>(
        ah, al, wqh, wql, b_qkv, nullptr, 3 * DIM, DIM);

    // 4) RoPE -> bf16 hi/lo q (pre-scaled), k
    const int nrope = TT * NH * 32;
    rope_split_kernel<<<(nrope + 255) / 256, 256>>>(cosT, sinT);

    // 5) Flash attention (mma.sync) -> bf16 hi/lo att output
    flash_mma<<<dim3(L_ / 128, NH, B_), 256, FL_SMEM>>>();

    // 6) Output projection -> d_out
    gemm_mma<0><<<dim3(DIM / 128, TT / 128), 256, GEMM_SMEM>>>(
        ath, atl, wph, wpl, b_proj, out, DIM, DIM);
}